// round 14
// baseline (speedup 1.0000x reference)
#include <cuda_runtime.h>
#include <cuda_fp16.h>
#include <math.h>

#define NN 100000
#define HH 64
#define EE 1600000
#define NSCAN_BLOCKS ((NN + 255) / 256)   // 391

// ---------------------------------------------------------------------------
// Scratch (__device__ globals; zero-initialized at module load, re-zeroed by
// the fused reset in the final agg launch -> every call sees zeros).
// ---------------------------------------------------------------------------
struct SetupState {
    int hist[NN];
    unsigned long long state[NSCAN_BLOCKS];  // lookback: (status<<32)|value
    unsigned int ticket;
};
__device__ SetupState d_setup;

__device__ int     d_rowptr[NN + 1];
__device__ int     d_cursor[NN];
__device__ int     d_csr   [EE];
__device__ float   d_dinv  [NN];
__device__ __half2 d_g    [(size_t)NN * (HH / 2)];  // gather payload (fp16)
__device__ __half2 d_bufA [(size_t)NN * (HH / 2)];  // prepped hidden (fp16)
__device__ __half2 d_bufB [(size_t)NN * (HH / 2)];

// ---------------------------------------------------------------------------
// Setup
// ---------------------------------------------------------------------------
__global__ void count_hist_kernel(const int* __restrict__ col, int E) {
    int e = blockIdx.x * blockDim.x + threadIdx.x;
    if (e < E) atomicAdd(&d_setup.hist[col[e]], 1);
}

// Single-pass exclusive scan (decoupled lookback) + rowptr/cursor/dinv.
__global__ void __launch_bounds__(256) scan_kernel(int n, int E) {
    __shared__ int sh[256];
    __shared__ int sh_bid;
    __shared__ int sh_excl;

    int t = threadIdx.x;
    if (t == 0) sh_bid = (int)atomicAdd(&d_setup.ticket, 1u);
    __syncthreads();
    int bid = sh_bid;

    int i = bid * 256 + t;
    int h = (i < n) ? d_setup.hist[i] : 0;
    sh[t] = h;
    __syncthreads();
    for (int off = 1; off < 256; off <<= 1) {
        int u = (t >= off) ? sh[t - off] : 0;
        __syncthreads();
        if (t >= off) sh[t] += u;
        __syncthreads();
    }
    int incl = sh[t];
    int total = sh[255];

    if (t == 0) {
        atomicExch(&d_setup.state[bid],
                   (1ull << 32) | (unsigned long long)(unsigned)total);
        int excl = 0;
        for (int p = bid - 1; p >= 0; ) {
            unsigned long long s;
            do { s = atomicAdd(&d_setup.state[p], 0ull); } while ((s >> 32) == 0ull);
            excl += (int)(unsigned)s;
            if ((s >> 32) == 2ull) break;
            p--;
        }
        atomicExch(&d_setup.state[bid],
                   (2ull << 32) | (unsigned long long)(unsigned)(excl + total));
        sh_excl = excl;
    }
    __syncthreads();

    if (i < n) {
        int v = sh_excl + incl - h;
        d_rowptr[i] = v;
        d_cursor[i] = v;
        d_dinv[i]   = rsqrtf((float)(1 + h));   // +1 self loop
    }
    if (i == 0) d_rowptr[n] = E;
}

__global__ void fill_kernel(const int* __restrict__ row,
                            const int* __restrict__ col, int E) {
    int e = blockIdx.x * blockDim.x + threadIdx.x;
    if (e < E) {
        int c = col[e];
        int p = atomicAdd(&d_cursor[c], 1);
        d_csr[p] = row[e];
    }
}

// ---------------------------------------------------------------------------
// Shared MMA core: 128x64 tile in xh (fp16, stride XH_STRIDE) @ wh -> g (fp16)
// Block 256 thr = 8 warps, warp = 16 rows. mma.sync.m16n8k16 f16->f32.
// ---------------------------------------------------------------------------
#define XH_STRIDE 72   // halves per row (144 B, 16B-aligned, conflict-free)
#define WH_STRIDE 72

__device__ __forceinline__ unsigned smem_u32(const void* p) {
    return (unsigned)__cvta_generic_to_shared(p);
}

__device__ __forceinline__ void mma_core(
    const __half* xh, const __half* wh, __half2* __restrict__ g,
    int row0, int n, int t)
{
    int warp = t >> 5, lane = t & 31;
    int gp = lane >> 2, q = lane & 3;
    int m0 = warp << 4;

    int lm  = lane & 7;
    int sel = lane >> 3;
    int a_row  = m0 + lm + ((sel & 1) << 3);
    int a_colh = (sel >> 1) << 3;
    unsigned aaddr = smem_u32(&xh[a_row * XH_STRIDE + a_colh]);

    int bk = lane & 15;
    unsigned baddr = smem_u32(&wh[bk * WH_STRIDE]);

    float acc[8][4];
#pragma unroll
    for (int j = 0; j < 8; j++)
#pragma unroll
        for (int i = 0; i < 4; i++) acc[j][i] = 0.f;

#pragma unroll
    for (int s = 0; s < 4; s++) {
        unsigned aa = aaddr + s * 32;
        unsigned a0, a1, a2, a3;
        asm volatile("ldmatrix.sync.aligned.m8n8.x4.shared.b16 {%0,%1,%2,%3}, [%4];"
                     : "=r"(a0), "=r"(a1), "=r"(a2), "=r"(a3) : "r"(aa));
        unsigned bs = baddr + s * (16 * WH_STRIDE * 2);
#pragma unroll
        for (int j = 0; j < 8; j++) {
            unsigned b0, b1;
            asm volatile("ldmatrix.sync.aligned.m8n8.x2.trans.shared.b16 {%0,%1}, [%2];"
                         : "=r"(b0), "=r"(b1) : "r"(bs + j * 16));
            asm volatile("mma.sync.aligned.m16n8k16.row.col.f32.f16.f16.f32 "
                         "{%0,%1,%2,%3}, {%4,%5,%6,%7}, {%8,%9}, {%0,%1,%2,%3};"
                         : "+f"(acc[j][0]), "+f"(acc[j][1]),
                           "+f"(acc[j][2]), "+f"(acc[j][3])
                         : "r"(a0), "r"(a1), "r"(a2), "r"(a3), "r"(b0), "r"(b1));
        }
    }

    int gr0 = row0 + m0 + gp;
    int gr1 = gr0 + 8;
    float d0 = (gr0 < n) ? d_dinv[gr0] : 0.f;
    float d1 = (gr1 < n) ? d_dinv[gr1] : 0.f;
#pragma unroll
    for (int j = 0; j < 8; j++) {
        int ci = 4 * j + q;
        if (gr0 < n)
            g[(size_t)gr0 * 32 + ci] = __floats2half2_rn(acc[j][0] * d0, acc[j][1] * d0);
        if (gr1 < n)
            g[(size_t)gr1 * 32 + ci] = __floats2half2_rn(acc[j][2] * d1, acc[j][3] * d1);
    }
}

// Layer 1: fp32 external input, no prep.
__global__ void __launch_bounds__(256) gemm_f32_kernel(
    const float* __restrict__ src, const float* __restrict__ W,
    __half2* __restrict__ g, int n)
{
    __shared__ __half xh[128 * XH_STRIDE];
    __shared__ __half wh[64 * WH_STRIDE];

    int t = threadIdx.x;
    int row0 = blockIdx.x << 7;

    for (int i = t; i < 4096; i += 256) {
        int k = i >> 6, c = i & 63;
        wh[k * WH_STRIDE + c] = __float2half(W[i]);
    }

    const float4* src4 = (const float4*)src;
#pragma unroll
    for (int j = 0; j < 8; j++) {
        int f  = t + (j << 8);
        int r  = f >> 4;
        int c4 = (f & 15) << 2;
        int gr = row0 + r;
        float4 v = make_float4(0.f, 0.f, 0.f, 0.f);
        if (gr < n) v = src4[(size_t)gr * 16 + (c4 >> 2)];
        *(__half2*)&xh[r * XH_STRIDE + c4]     = __floats2half2_rn(v.x, v.y);
        *(__half2*)&xh[r * XH_STRIDE + c4 + 2] = __floats2half2_rn(v.z, v.w);
    }
    __syncthreads();

    mma_core(xh, wh, g, row0, n, t);
}

// Layers 2,3: fp16 pre-prepped input via cp.async.
__global__ void __launch_bounds__(256) gemm_f16_kernel(
    const __half2* __restrict__ src, const float* __restrict__ W,
    __half2* __restrict__ g, int n)
{
    __shared__ __half xh[128 * XH_STRIDE];
    __shared__ __half wh[64 * WH_STRIDE];

    int t = threadIdx.x;
    int row0 = blockIdx.x << 7;

#pragma unroll
    for (int j = 0; j < 4; j++) {
        int f  = t + (j << 8);              // chunk id 0..1023
        int r  = f >> 3;
        int c8 = (f & 7) << 3;              // halves offset in row
        int gr = row0 + r;
        unsigned daddr = smem_u32(&xh[r * XH_STRIDE + c8]);
        const void* gptr = (const void*)(src + ((gr < n) ? ((size_t)gr * 32 + (c8 >> 1)) : 0));
        int srcsz = (gr < n) ? 16 : 0;      // zero-fill OOB rows
        asm volatile("cp.async.cg.shared.global [%0], [%1], 16, %2;"
                     :: "r"(daddr), "l"(gptr), "r"(srcsz));
    }
    asm volatile("cp.async.commit_group;");

    for (int i = t; i < 4096; i += 256) {
        int k = i >> 6, c = i & 63;
        wh[k * WH_STRIDE + c] = __float2half(W[i]);
    }

    asm volatile("cp.async.wait_group 0;");
    __syncthreads();

    mma_core(xh, wh, g, row0, n, t);
}

// ---------------------------------------------------------------------------
// Aggregation v3: warp per node, FOUR edges per LDG.128.
// lane = (sub, oct): sub = lane>>3 selects edge within quad, oct = lane&7
// selects the 16 B feature chunk (8 halves). Cross-sub partials combined by
// 2 butterfly shuffles at the end. Bytes identical to v2; 8x fewer LDGs.
//   mode 0: buf[c] = fp16( elu(acc*dinv + b) )      (hidden layers)
//   mode 1: out[c] = fp32( acc*dinv + b )           (final layer)
// do_reset: fused scratch re-zero (final launch only).
// ---------------------------------------------------------------------------
__device__ __forceinline__ void acc16(uint4 v, float2 a[4]) {
    __half2 h0 = *(__half2*)&v.x, h1 = *(__half2*)&v.y;
    __half2 h2 = *(__half2*)&v.z, h3 = *(__half2*)&v.w;
    float2 f0 = __half22float2(h0), f1 = __half22float2(h1);
    float2 f2 = __half22float2(h2), f3 = __half22float2(h3);
    a[0].x += f0.x; a[0].y += f0.y;
    a[1].x += f1.x; a[1].y += f1.y;
    a[2].x += f2.x; a[2].y += f2.y;
    a[3].x += f3.x; a[3].y += f3.y;
}

__global__ void __launch_bounds__(256) agg_kernel(
    const uint4* __restrict__ g4, void* __restrict__ outv,
    int n, int mode, const float* __restrict__ b, int do_reset)
{
    int gt   = blockIdx.x * 256 + threadIdx.x;
    if (do_reset) {
        if (gt < NN) d_setup.hist[gt] = 0;
        if (gt < NSCAN_BLOCKS) d_setup.state[gt] = 0ull;
        if (gt == 0) d_setup.ticket = 0u;
    }

    int w    = gt >> 5;
    int lane = threadIdx.x & 31;
    if (w >= n) return;
    int sub = lane >> 3;     // edge slot within quad
    int oct = lane & 7;      // 16B feature chunk

    float2 a[4] = {{0.f,0.f},{0.f,0.f},{0.f,0.f},{0.f,0.f}};

    // self loop: sub 0 lanes only (added once)
    if (sub == 0) acc16(g4[(size_t)w * 8 + oct], a);

    int s = d_rowptr[w];
    int e = d_rowptr[w + 1];
    int i = s;

    for (; i + 8 <= e; i += 8) {
        int ia = d_csr[i + sub];
        int ib = d_csr[i + 4 + sub];
        uint4 va = g4[(size_t)ia * 8 + oct];
        uint4 vb = g4[(size_t)ib * 8 + oct];
        acc16(va, a);
        acc16(vb, a);
    }
    if (i + 4 <= e) {
        int ia = d_csr[i + sub];
        uint4 va = g4[(size_t)ia * 8 + oct];
        acc16(va, a);
        i += 4;
    }
    int rem = e - i;                       // 0..3
    if (rem > 0) {
        int idx = d_csr[(sub < rem) ? (i + sub) : i];
        uint4 v = g4[(size_t)idx * 8 + oct];
        if (sub < rem) acc16(v, a);
    }

    // combine partials across the 4 sub-slots (lanes oct, oct+8, oct+16, oct+24)
#pragma unroll
    for (int j = 0; j < 4; j++) {
        a[j].x += __shfl_xor_sync(0xffffffffu, a[j].x, 8);
        a[j].y += __shfl_xor_sync(0xffffffffu, a[j].y, 8);
        a[j].x += __shfl_xor_sync(0xffffffffu, a[j].x, 16);
        a[j].y += __shfl_xor_sync(0xffffffffu, a[j].y, 16);
    }

    float dv = d_dinv[w];
    const float2* b2 = (const float2*)b;   // feature pairs: chunk oct -> [oct*4 .. oct*4+3]
    if (mode == 0) {
        __half2 h[4];
#pragma unroll
        for (int j = 0; j < 4; j++) {
            float2 bb = b2[oct * 4 + j];
            float x = a[j].x * dv + bb.x;  x = (x > 0.f) ? x : expm1f(x);
            float y = a[j].y * dv + bb.y;  y = (y > 0.f) ? y : expm1f(y);
            h[j] = __floats2half2_rn(x, y);
        }
        if (sub == 0)
            ((uint4*)outv)[(size_t)w * 8 + oct] = *(uint4*)h;
    } else {
        float o[8];
#pragma unroll
        for (int j = 0; j < 4; j++) {
            float2 bb = b2[oct * 4 + j];
            o[2 * j]     = a[j].x * dv + bb.x;
            o[2 * j + 1] = a[j].y * dv + bb.y;
        }
        if (sub == 0) {
            float4* op = (float4*)outv + (size_t)w * 16 + oct * 2;
            op[0] = make_float4(o[0], o[1], o[2], o[3]);
            op[1] = make_float4(o[4], o[5], o[6], o[7]);
        }
    }
}

// ---------------------------------------------------------------------------
extern "C" void kernel_launch(void* const* d_in, const int* in_sizes, int n_in,
                              void* d_out, int out_size)
{
    const float* x  = (const float*)d_in[0];
    const int*   ei = (const int*)  d_in[1];
    const float* W1 = (const float*)d_in[2];
    const float* b1 = (const float*)d_in[3];
    const float* W2 = (const float*)d_in[4];
    const float* b2 = (const float*)d_in[5];
    const float* W3 = (const float*)d_in[6];
    const float* b3 = (const float*)d_in[7];

    int n = in_sizes[0] / HH;   // 100000
    int E = in_sizes[1] / 2;    // 1600000
    const int* row = ei;        // sources
    const int* col = ei + E;    // targets

    void *g_p, *A_p, *B_p;
    cudaGetSymbolAddress(&g_p, d_g);
    cudaGetSymbolAddress(&A_p, d_bufA);
    cudaGetSymbolAddress(&B_p, d_bufB);
    __half2*     g  = (__half2*)g_p;
    const uint4* g4 = (const uint4*)g_p;
    __half2*     A  = (__half2*)A_p;
    __half2*     B  = (__half2*)B_p;

    int nbE = (E + 255) / 256;

    // ---- CSR build (d_setup arrives zeroed; agg3 re-zeroes it) ----
    count_hist_kernel<<<nbE, 256>>>(col, E);
    scan_kernel<<<NSCAN_BLOCKS, 256>>>(n, E);
    fill_kernel<<<nbE, 256>>>(row, col, E);

    int gblocks = (n + 127) / 128;                      // 782
    int ablocks = (n * 32 + 255) / 256;                 // one warp per node

    // Layer 1
    gemm_f32_kernel<<<gblocks, 256>>>(x, W1, g, n);
    agg_kernel<<<ablocks, 256>>>(g4, A, n, 0, b1, 0);
    // Layer 2
    gemm_f16_kernel<<<gblocks, 256>>>(A, W2, g, n);
    agg_kernel<<<ablocks, 256>>>(g4, B, n, 0, b2, 0);
    // Layer 3
    gemm_f16_kernel<<<gblocks, 256>>>(B, W3, g, n);
    agg_kernel<<<ablocks, 256>>>(g4, d_out, n, 1, b3, 1);  // + fused reset
}

// round 15
// speedup vs baseline: 1.1525x; 1.1525x over previous
#include <cuda_runtime.h>
#include <cuda_fp16.h>
#include <math.h>

#define NN 100000
#define HH 64
#define EE 1600000
#define NSCAN_BLOCKS ((NN + 255) / 256)   // 391

// ---------------------------------------------------------------------------
// Scratch (__device__ globals; zero-initialized at module load, re-zeroed by
// the fused reset in the final agg launch -> every call sees zeros).
// ---------------------------------------------------------------------------
struct SetupState {
    int hist[NN];
    unsigned long long state[NSCAN_BLOCKS];  // lookback: (status<<32)|value
    unsigned int ticket;
};
__device__ SetupState d_setup;

__device__ int     d_rowptr[NN + 1];
__device__ int     d_cursor[NN];
__device__ int     d_csr   [EE];
__device__ float   d_dinv  [NN];
__device__ __half2 d_g    [(size_t)NN * (HH / 2)];  // gather payload (fp16)
__device__ __half2 d_bufA [(size_t)NN * (HH / 2)];  // prepped hidden (fp16)
__device__ __half2 d_bufB [(size_t)NN * (HH / 2)];

// ---------------------------------------------------------------------------
// Setup
// ---------------------------------------------------------------------------
__global__ void count_hist_kernel(const int* __restrict__ col, int E) {
    int e = blockIdx.x * blockDim.x + threadIdx.x;
    if (e < E) atomicAdd(&d_setup.hist[col[e]], 1);
}

// Single-pass exclusive scan (decoupled lookback) + rowptr/cursor/dinv.
__global__ void __launch_bounds__(256) scan_kernel(int n, int E) {
    __shared__ int sh[256];
    __shared__ int sh_bid;
    __shared__ int sh_excl;

    int t = threadIdx.x;
    if (t == 0) sh_bid = (int)atomicAdd(&d_setup.ticket, 1u);
    __syncthreads();
    int bid = sh_bid;

    int i = bid * 256 + t;
    int h = (i < n) ? d_setup.hist[i] : 0;
    sh[t] = h;
    __syncthreads();
    for (int off = 1; off < 256; off <<= 1) {
        int u = (t >= off) ? sh[t - off] : 0;
        __syncthreads();
        if (t >= off) sh[t] += u;
        __syncthreads();
    }
    int incl = sh[t];
    int total = sh[255];

    if (t == 0) {
        atomicExch(&d_setup.state[bid],
                   (1ull << 32) | (unsigned long long)(unsigned)total);
        int excl = 0;
        for (int p = bid - 1; p >= 0; ) {
            unsigned long long s;
            do { s = atomicAdd(&d_setup.state[p], 0ull); } while ((s >> 32) == 0ull);
            excl += (int)(unsigned)s;
            if ((s >> 32) == 2ull) break;
            p--;
        }
        atomicExch(&d_setup.state[bid],
                   (2ull << 32) | (unsigned long long)(unsigned)(excl + total));
        sh_excl = excl;
    }
    __syncthreads();

    if (i < n) {
        int v = sh_excl + incl - h;
        d_rowptr[i] = v;
        d_cursor[i] = v;
        d_dinv[i]   = rsqrtf((float)(1 + h));   // +1 self loop
    }
    if (i == 0) d_rowptr[n] = E;
}

// ---------------------------------------------------------------------------
// MMA core: 128x64 tile in xh (fp16, stride XH_STRIDE) @ wh -> g (fp16)
// 256 thr = 8 warps, warp = 16 rows. mma.sync.m16n8k16 f16->f32.
// ---------------------------------------------------------------------------
#define XH_STRIDE 72   // halves per row (144 B, 16B-aligned, conflict-free)
#define WH_STRIDE 72

__device__ __forceinline__ unsigned smem_u32(const void* p) {
    return (unsigned)__cvta_generic_to_shared(p);
}

__device__ __forceinline__ void mma_core(
    const __half* xh, const __half* wh, __half2* __restrict__ g,
    int row0, int n, int t)
{
    int warp = t >> 5, lane = t & 31;
    int gp = lane >> 2, q = lane & 3;
    int m0 = warp << 4;

    int lm  = lane & 7;
    int sel = lane >> 3;
    int a_row  = m0 + lm + ((sel & 1) << 3);
    int a_colh = (sel >> 1) << 3;
    unsigned aaddr = smem_u32(&xh[a_row * XH_STRIDE + a_colh]);

    int bk = lane & 15;
    unsigned baddr = smem_u32(&wh[bk * WH_STRIDE]);

    float acc[8][4];
#pragma unroll
    for (int j = 0; j < 8; j++)
#pragma unroll
        for (int i = 0; i < 4; i++) acc[j][i] = 0.f;

#pragma unroll
    for (int s = 0; s < 4; s++) {
        unsigned aa = aaddr + s * 32;
        unsigned a0, a1, a2, a3;
        asm volatile("ldmatrix.sync.aligned.m8n8.x4.shared.b16 {%0,%1,%2,%3}, [%4];"
                     : "=r"(a0), "=r"(a1), "=r"(a2), "=r"(a3) : "r"(aa));
        unsigned bs = baddr + s * (16 * WH_STRIDE * 2);
#pragma unroll
        for (int j = 0; j < 8; j++) {
            unsigned b0, b1;
            asm volatile("ldmatrix.sync.aligned.m8n8.x2.trans.shared.b16 {%0,%1}, [%2];"
                         : "=r"(b0), "=r"(b1) : "r"(bs + j * 16));
            asm volatile("mma.sync.aligned.m16n8k16.row.col.f32.f16.f16.f32 "
                         "{%0,%1,%2,%3}, {%4,%5,%6,%7}, {%8,%9}, {%0,%1,%2,%3};"
                         : "+f"(acc[j][0]), "+f"(acc[j][1]),
                           "+f"(acc[j][2]), "+f"(acc[j][3])
                         : "r"(a0), "r"(a1), "r"(a2), "r"(a3), "r"(b0), "r"(b1));
        }
    }

    int gr0 = row0 + m0 + gp;
    int gr1 = gr0 + 8;
    float d0 = (gr0 < n) ? d_dinv[gr0] : 0.f;
    float d1 = (gr1 < n) ? d_dinv[gr1] : 0.f;
#pragma unroll
    for (int j = 0; j < 8; j++) {
        int ci = 4 * j + q;
        if (gr0 < n)
            g[(size_t)gr0 * 32 + ci] = __floats2half2_rn(acc[j][0] * d0, acc[j][1] * d0);
        if (gr1 < n)
            g[(size_t)gr1 * 32 + ci] = __floats2half2_rn(acc[j][2] * d1, acc[j][3] * d1);
    }
}

// ---------------------------------------------------------------------------
// Fused launch 3: blocks [0, gblocks) do layer-1 GEMM (fp32 x @ W1 -> g);
// blocks [gblocks, gblocks+fblocks) do CSR bucket fill. The two parts touch
// disjoint state and both depend only on scan_kernel.
// ---------------------------------------------------------------------------
__global__ void __launch_bounds__(256) gemm1_fill_kernel(
    const float* __restrict__ src, const float* __restrict__ W,
    __half2* __restrict__ g, int n, int gblocks,
    const int* __restrict__ row, const int* __restrict__ col, int E)
{
    __shared__ __half xh[128 * XH_STRIDE];
    __shared__ __half wh[64 * WH_STRIDE];

    int t = threadIdx.x;

    if (blockIdx.x >= gblocks) {
        // ---- fill part ----
        int e = (blockIdx.x - gblocks) * 256 + t;
        if (e < E) {
            int c = col[e];
            int p = atomicAdd(&d_cursor[c], 1);
            d_csr[p] = row[e];
        }
        return;
    }

    // ---- gemm part (layer 1, fp32 input) ----
    int row0 = blockIdx.x << 7;

    for (int i = t; i < 4096; i += 256) {
        int k = i >> 6, c = i & 63;
        wh[k * WH_STRIDE + c] = __float2half(W[i]);
    }

    const float4* src4 = (const float4*)src;
#pragma unroll
    for (int j = 0; j < 8; j++) {
        int f  = t + (j << 8);
        int r  = f >> 4;
        int c4 = (f & 15) << 2;
        int gr = row0 + r;
        float4 v = make_float4(0.f, 0.f, 0.f, 0.f);
        if (gr < n) v = src4[(size_t)gr * 16 + (c4 >> 2)];
        *(__half2*)&xh[r * XH_STRIDE + c4]     = __floats2half2_rn(v.x, v.y);
        *(__half2*)&xh[r * XH_STRIDE + c4 + 2] = __floats2half2_rn(v.z, v.w);
    }
    __syncthreads();

    mma_core(xh, wh, g, row0, n, t);
}

// Layers 2,3: fp16 pre-prepped input via cp.async.
__global__ void __launch_bounds__(256) gemm_f16_kernel(
    const __half2* __restrict__ src, const float* __restrict__ W,
    __half2* __restrict__ g, int n)
{
    __shared__ __half xh[128 * XH_STRIDE];
    __shared__ __half wh[64 * WH_STRIDE];

    int t = threadIdx.x;
    int row0 = blockIdx.x << 7;

#pragma unroll
    for (int j = 0; j < 4; j++) {
        int f  = t + (j << 8);              // chunk id 0..1023
        int r  = f >> 3;
        int c8 = (f & 7) << 3;              // halves offset in row
        int gr = row0 + r;
        unsigned daddr = smem_u32(&xh[r * XH_STRIDE + c8]);
        const void* gptr = (const void*)(src + ((gr < n) ? ((size_t)gr * 32 + (c8 >> 1)) : 0));
        int srcsz = (gr < n) ? 16 : 0;      // zero-fill OOB rows
        asm volatile("cp.async.cg.shared.global [%0], [%1], 16, %2;"
                     :: "r"(daddr), "l"(gptr), "r"(srcsz));
    }
    asm volatile("cp.async.commit_group;");

    for (int i = t; i < 4096; i += 256) {
        int k = i >> 6, c = i & 63;
        wh[k * WH_STRIDE + c] = __float2half(W[i]);
    }

    asm volatile("cp.async.wait_group 0;");
    __syncthreads();

    mma_core(xh, wh, g, row0, n, t);
}

// ---------------------------------------------------------------------------
// Aggregation (v2, best observed): ONE node per warp, unroll-8 gathers,
// half2 per lane (one 128B line per edge). fp32 accumulation.
//   mode 0: buf[c] = fp16( elu(acc*dinv + b) )      (hidden layers)
//   mode 1: out[c] = fp32( acc*dinv + b )           (final layer)
// do_reset: fused scratch re-zero (final launch only).
// ---------------------------------------------------------------------------
__global__ void __launch_bounds__(256) agg_kernel(
    const __half2* __restrict__ g, void* __restrict__ outv,
    int n, int mode, const float* __restrict__ b, int do_reset)
{
    int gt = blockIdx.x * 256 + threadIdx.x;
    if (do_reset) {
        if (gt < NN) d_setup.hist[gt] = 0;
        if (gt < NSCAN_BLOCKS) d_setup.state[gt] = 0ull;
        if (gt == 0) d_setup.ticket = 0u;
    }

    int w    = gt >> 5;
    int lane = threadIdx.x & 31;
    if (w >= n) return;

    float2 acc = __half22float2(g[(size_t)w * 32 + lane]);   // self loop

    int s = d_rowptr[w];
    int e = d_rowptr[w + 1];
    int i = s;

    for (; i + 8 <= e; i += 8) {
        int r0 = d_csr[i],     r1 = d_csr[i + 1], r2 = d_csr[i + 2], r3 = d_csr[i + 3];
        int r4 = d_csr[i + 4], r5 = d_csr[i + 5], r6 = d_csr[i + 6], r7 = d_csr[i + 7];
        float2 v0 = __half22float2(g[(size_t)r0 * 32 + lane]);
        float2 v1 = __half22float2(g[(size_t)r1 * 32 + lane]);
        float2 v2 = __half22float2(g[(size_t)r2 * 32 + lane]);
        float2 v3 = __half22float2(g[(size_t)r3 * 32 + lane]);
        float2 v4 = __half22float2(g[(size_t)r4 * 32 + lane]);
        float2 v5 = __half22float2(g[(size_t)r5 * 32 + lane]);
        float2 v6 = __half22float2(g[(size_t)r6 * 32 + lane]);
        float2 v7 = __half22float2(g[(size_t)r7 * 32 + lane]);
        acc.x += (v0.x + v1.x) + (v2.x + v3.x) + ((v4.x + v5.x) + (v6.x + v7.x));
        acc.y += (v0.y + v1.y) + (v2.y + v3.y) + ((v4.y + v5.y) + (v6.y + v7.y));
    }
    if (i + 4 <= e) {
        int r0 = d_csr[i], r1 = d_csr[i + 1], r2 = d_csr[i + 2], r3 = d_csr[i + 3];
        float2 v0 = __half22float2(g[(size_t)r0 * 32 + lane]);
        float2 v1 = __half22float2(g[(size_t)r1 * 32 + lane]);
        float2 v2 = __half22float2(g[(size_t)r2 * 32 + lane]);
        float2 v3 = __half22float2(g[(size_t)r3 * 32 + lane]);
        acc.x += (v0.x + v1.x) + (v2.x + v3.x);
        acc.y += (v0.y + v1.y) + (v2.y + v3.y);
        i += 4;
    }
    for (; i < e; i++) {
        float2 v = __half22float2(g[(size_t)d_csr[i] * 32 + lane]);
        acc.x += v.x; acc.y += v.y;
    }

    float2 bb = ((const float2*)b)[lane];
    float dv = d_dinv[w];
    if (mode == 0) {
        float x0 = acc.x * dv + bb.x;  x0 = (x0 > 0.f) ? x0 : expm1f(x0);
        float y0 = acc.y * dv + bb.y;  y0 = (y0 > 0.f) ? y0 : expm1f(y0);
        ((__half2*)outv)[(size_t)w * 32 + lane] = __floats2half2_rn(x0, y0);
    } else {
        ((float2*)outv)[(size_t)w * 32 + lane] =
            make_float2(acc.x * dv + bb.x, acc.y * dv + bb.y);
    }
}

// ---------------------------------------------------------------------------
extern "C" void kernel_launch(void* const* d_in, const int* in_sizes, int n_in,
                              void* d_out, int out_size)
{
    const float* x  = (const float*)d_in[0];
    const int*   ei = (const int*)  d_in[1];
    const float* W1 = (const float*)d_in[2];
    const float* b1 = (const float*)d_in[3];
    const float* W2 = (const float*)d_in[4];
    const float* b2 = (const float*)d_in[5];
    const float* W3 = (const float*)d_in[6];
    const float* b3 = (const float*)d_in[7];

    int n = in_sizes[0] / HH;   // 100000
    int E = in_sizes[1] / 2;    // 1600000
    const int* row = ei;        // sources
    const int* col = ei + E;    // targets

    void *g_p, *A_p, *B_p;
    cudaGetSymbolAddress(&g_p, d_g);
    cudaGetSymbolAddress(&A_p, d_bufA);
    cudaGetSymbolAddress(&B_p, d_bufB);
    __half2* g = (__half2*)g_p;
    __half2* A = (__half2*)A_p;
    __half2* B = (__half2*)B_p;

    int nbE     = (E + 255) / 256;                      // 6250
    int gblocks = (n + 127) / 128;                      // 782
    int ablocks = (n * 32 + 255) / 256;                 // one warp per node

    // launch 1: target histogram
    count_hist_kernel<<<nbE, 256>>>(col, E);
    // launch 2: scan -> rowptr/cursor/dinv
    scan_kernel<<<NSCAN_BLOCKS, 256>>>(n, E);
    // launch 3 (fused): layer-1 GEMM + CSR fill (independent parts)
    gemm1_fill_kernel<<<gblocks + nbE, 256>>>(x, W1, g, n, gblocks, row, col, E);
    // launch 4: agg1  <- ncu capture slot
    agg_kernel<<<ablocks, 256>>>(g, A, n, 0, b1, 0);
    // Layer 2
    gemm_f16_kernel<<<gblocks, 256>>>(A, W2, g, n);
    agg_kernel<<<ablocks, 256>>>(g, B, n, 0, b2, 0);
    // Layer 3
    gemm_f16_kernel<<<gblocks, 256>>>(B, W3, g, n);
    agg_kernel<<<ablocks, 256>>>(g, d_out, n, 1, b3, 1);   // + fused reset
}

// round 16
// speedup vs baseline: 1.2827x; 1.1130x over previous
#include <cuda_runtime.h>
#include <cuda_fp16.h>
#include <math.h>

#define NN 100000
#define HH 64
#define EE 1600000
#define NSCAN_BLOCKS ((NN + 255) / 256)   // 391
#define CSRCAP (EE + 3 * NN)              // quad-padded CSR capacity (1.9M)

// ---------------------------------------------------------------------------
// Scratch (__device__ globals; zero-initialized at module load, re-zeroed by
// the fused reset in the final agg launch -> every call sees zeros).
// ---------------------------------------------------------------------------
struct SetupState {
    int hist[NN];
    unsigned long long state[NSCAN_BLOCKS];  // lookback: (status<<32)|value
    unsigned int ticket;
};
__device__ SetupState d_setup;

__device__ int     d_rowptr[NN + 1];
__device__ int     d_cursor[NN];
__device__ int     d_csr   [CSRCAP];
__device__ float   d_dinv  [NN];
// Row NN is a permanent all-zero dummy row (never written by any gemm).
__device__ __half2 d_g    [(size_t)(NN + 1) * (HH / 2)];
__device__ __half2 d_bufA [(size_t)NN * (HH / 2)];
__device__ __half2 d_bufB [(size_t)NN * (HH / 2)];

// ---------------------------------------------------------------------------
// Setup
// ---------------------------------------------------------------------------
// Launch 1: target histogram + prefill csr with dummy index NN (holes left by
// fill_kernel then point at the zero row -> no remainder handling in agg).
__global__ void count_hist_kernel(const int* __restrict__ col, int E) {
    int e = blockIdx.x * blockDim.x + threadIdx.x;
    if (e < E) atomicAdd(&d_setup.hist[col[e]], 1);
    int total = gridDim.x * blockDim.x;
    for (int i = e; i < CSRCAP; i += total) d_csr[i] = NN;
}

// Launch 2: single-pass exclusive scan (decoupled lookback) over quad-padded
// degrees -> aligned rowptr/cursor, plus dinv.
__global__ void __launch_bounds__(256) scan_kernel(int n) {
    __shared__ int sh[256];
    __shared__ int sh_bid;
    __shared__ int sh_excl;

    int t = threadIdx.x;
    if (t == 0) sh_bid = (int)atomicAdd(&d_setup.ticket, 1u);
    __syncthreads();
    int bid = sh_bid;

    int i = bid * 256 + t;
    int h  = (i < n) ? d_setup.hist[i] : 0;
    int pd = (h + 3) & ~3;                  // quad-padded degree
    sh[t] = pd;
    __syncthreads();
    for (int off = 1; off < 256; off <<= 1) {
        int u = (t >= off) ? sh[t - off] : 0;
        __syncthreads();
        if (t >= off) sh[t] += u;
        __syncthreads();
    }
    int incl = sh[t];
    int total = sh[255];

    if (t == 0) {
        atomicExch(&d_setup.state[bid],
                   (1ull << 32) | (unsigned long long)(unsigned)total);
        int excl = 0;
        for (int p = bid - 1; p >= 0; ) {
            unsigned long long s;
            do { s = atomicAdd(&d_setup.state[p], 0ull); } while ((s >> 32) == 0ull);
            excl += (int)(unsigned)s;
            if ((s >> 32) == 2ull) break;
            p--;
        }
        atomicExch(&d_setup.state[bid],
                   (2ull << 32) | (unsigned long long)(unsigned)(excl + total));
        sh_excl = excl;
    }
    __syncthreads();

    if (i < n) {
        int v = sh_excl + incl - pd;        // aligned exclusive prefix
        d_rowptr[i] = v;
        d_cursor[i] = v;
        d_dinv[i]   = rsqrtf((float)(1 + h));   // +1 self loop
        if (i == n - 1) d_rowptr[n] = v + pd;
    }
}

// ---------------------------------------------------------------------------
// MMA core: 128x64 tile in xh (fp16, stride XH_STRIDE) @ wh -> g (fp16)
// 256 thr = 8 warps, warp = 16 rows. mma.sync.m16n8k16 f16->f32.
// ---------------------------------------------------------------------------
#define XH_STRIDE 72   // halves per row (144 B, 16B-aligned, conflict-free)
#define WH_STRIDE 72

__device__ __forceinline__ unsigned smem_u32(const void* p) {
    return (unsigned)__cvta_generic_to_shared(p);
}

__device__ __forceinline__ void mma_core(
    const __half* xh, const __half* wh, __half2* __restrict__ g,
    int row0, int n, int t)
{
    int warp = t >> 5, lane = t & 31;
    int gp = lane >> 2, q = lane & 3;
    int m0 = warp << 4;

    int lm  = lane & 7;
    int sel = lane >> 3;
    int a_row  = m0 + lm + ((sel & 1) << 3);
    int a_colh = (sel >> 1) << 3;
    unsigned aaddr = smem_u32(&xh[a_row * XH_STRIDE + a_colh]);

    int bk = lane & 15;
    unsigned baddr = smem_u32(&wh[bk * WH_STRIDE]);

    float acc[8][4];
#pragma unroll
    for (int j = 0; j < 8; j++)
#pragma unroll
        for (int i = 0; i < 4; i++) acc[j][i] = 0.f;

#pragma unroll
    for (int s = 0; s < 4; s++) {
        unsigned aa = aaddr + s * 32;
        unsigned a0, a1, a2, a3;
        asm volatile("ldmatrix.sync.aligned.m8n8.x4.shared.b16 {%0,%1,%2,%3}, [%4];"
                     : "=r"(a0), "=r"(a1), "=r"(a2), "=r"(a3) : "r"(aa));
        unsigned bs = baddr + s * (16 * WH_STRIDE * 2);
#pragma unroll
        for (int j = 0; j < 8; j++) {
            unsigned b0, b1;
            asm volatile("ldmatrix.sync.aligned.m8n8.x2.trans.shared.b16 {%0,%1}, [%2];"
                         : "=r"(b0), "=r"(b1) : "r"(bs + j * 16));
            asm volatile("mma.sync.aligned.m16n8k16.row.col.f32.f16.f16.f32 "
                         "{%0,%1,%2,%3}, {%4,%5,%6,%7}, {%8,%9}, {%0,%1,%2,%3};"
                         : "+f"(acc[j][0]), "+f"(acc[j][1]),
                           "+f"(acc[j][2]), "+f"(acc[j][3])
                         : "r"(a0), "r"(a1), "r"(a2), "r"(a3), "r"(b0), "r"(b1));
        }
    }

    int gr0 = row0 + m0 + gp;
    int gr1 = gr0 + 8;
    float d0 = (gr0 < n) ? d_dinv[gr0] : 0.f;
    float d1 = (gr1 < n) ? d_dinv[gr1] : 0.f;
#pragma unroll
    for (int j = 0; j < 8; j++) {
        int ci = 4 * j + q;
        if (gr0 < n)
            g[(size_t)gr0 * 32 + ci] = __floats2half2_rn(acc[j][0] * d0, acc[j][1] * d0);
        if (gr1 < n)
            g[(size_t)gr1 * 32 + ci] = __floats2half2_rn(acc[j][2] * d1, acc[j][3] * d1);
    }
}

// ---------------------------------------------------------------------------
// Fused launch 3: blocks [0, gblocks) do layer-1 GEMM (fp32 x @ W1 -> g);
// blocks [gblocks, ...) do CSR bucket fill (independent state, both depend
// only on scan_kernel).
// ---------------------------------------------------------------------------
__global__ void __launch_bounds__(256) gemm1_fill_kernel(
    const float* __restrict__ src, const float* __restrict__ W,
    __half2* __restrict__ g, int n, int gblocks,
    const int* __restrict__ row, const int* __restrict__ col, int E)
{
    __shared__ __half xh[128 * XH_STRIDE];
    __shared__ __half wh[64 * WH_STRIDE];

    int t = threadIdx.x;

    if (blockIdx.x >= gblocks) {
        int e = (blockIdx.x - gblocks) * 256 + t;
        if (e < E) {
            int c = col[e];
            int p = atomicAdd(&d_cursor[c], 1);
            d_csr[p] = row[e];
        }
        return;
    }

    int row0 = blockIdx.x << 7;

    for (int i = t; i < 4096; i += 256) {
        int k = i >> 6, c = i & 63;
        wh[k * WH_STRIDE + c] = __float2half(W[i]);
    }

    const float4* src4 = (const float4*)src;
#pragma unroll
    for (int j = 0; j < 8; j++) {
        int f  = t + (j << 8);
        int r  = f >> 4;
        int c4 = (f & 15) << 2;
        int gr = row0 + r;
        float4 v = make_float4(0.f, 0.f, 0.f, 0.f);
        if (gr < n) v = src4[(size_t)gr * 16 + (c4 >> 2)];
        *(__half2*)&xh[r * XH_STRIDE + c4]     = __floats2half2_rn(v.x, v.y);
        *(__half2*)&xh[r * XH_STRIDE + c4 + 2] = __floats2half2_rn(v.z, v.w);
    }
    __syncthreads();

    mma_core(xh, wh, g, row0, n, t);
}

// Layers 2,3: fp16 pre-prepped input via cp.async.
__global__ void __launch_bounds__(256) gemm_f16_kernel(
    const __half2* __restrict__ src, const float* __restrict__ W,
    __half2* __restrict__ g, int n)
{
    __shared__ __half xh[128 * XH_STRIDE];
    __shared__ __half wh[64 * WH_STRIDE];

    int t = threadIdx.x;
    int row0 = blockIdx.x << 7;

#pragma unroll
    for (int j = 0; j < 4; j++) {
        int f  = t + (j << 8);              // chunk id 0..1023
        int r  = f >> 3;
        int c8 = (f & 7) << 3;              // halves offset in row
        int gr = row0 + r;
        unsigned daddr = smem_u32(&xh[r * XH_STRIDE + c8]);
        const void* gptr = (const void*)(src + ((gr < n) ? ((size_t)gr * 32 + (c8 >> 1)) : 0));
        int srcsz = (gr < n) ? 16 : 0;      // zero-fill OOB rows
        asm volatile("cp.async.cg.shared.global [%0], [%1], 16, %2;"
                     :: "r"(daddr), "l"(gptr), "r"(srcsz));
    }
    asm volatile("cp.async.commit_group;");

    for (int i = t; i < 4096; i += 256) {
        int k = i >> 6, c = i & 63;
        wh[k * WH_STRIDE + c] = __float2half(W[i]);
    }

    asm volatile("cp.async.wait_group 0;");
    __syncthreads();

    mma_core(xh, wh, g, row0, n, t);
}

// ---------------------------------------------------------------------------
// Aggregation v4 (instruction-minimized): warp per node, quad-aligned CSR.
// Per 4 edges: 1 uniform LDG.128 (4 indices) + 4 payload LDG.32 + 2 HADD2
// (fp16 pairwise) + 2 cvt + 2 packed add.rn.f32x2. No remainder handling —
// holes point at the permanent zero row NN.
//   mode 0: buf[c] = fp16( elu(acc*dinv + b) )      (hidden layers)
//   mode 1: out[c] = fp32( acc*dinv + b )           (final layer)
// ---------------------------------------------------------------------------
__global__ void __launch_bounds__(256) agg_kernel(
    const __half2* __restrict__ g, void* __restrict__ outv,
    int n, int mode, const float* __restrict__ b, int do_reset)
{
    int gt = blockIdx.x * 256 + threadIdx.x;
    if (do_reset) {
        if (gt < NN) d_setup.hist[gt] = 0;
        if (gt < NSCAN_BLOCKS) d_setup.state[gt] = 0ull;
        if (gt == 0) d_setup.ticket = 0u;
    }

    int w    = gt >> 5;
    int lane = threadIdx.x & 31;
    if (w >= n) return;

    const __half2* gl = g + lane;           // per-lane base

    float2 acc = __half22float2(gl[(size_t)w * 32]);   // self loop
    unsigned long long accp;
    asm("mov.b64 %0, {%1,%2};" : "=l"(accp) : "f"(acc.x), "f"(acc.y));

    int s = d_rowptr[w];
    int e = d_rowptr[w + 1];                 // quad-aligned span (holes = row NN)
    int i = s;

    for (; i + 8 <= e; i += 8) {
        int4 ra = *(const int4*)&d_csr[i];
        int4 rb = *(const int4*)&d_csr[i + 4];
        __half2 a0 = gl[(size_t)ra.x * 32];
        __half2 a1 = gl[(size_t)ra.y * 32];
        __half2 a2 = gl[(size_t)ra.z * 32];
        __half2 a3 = gl[(size_t)ra.w * 32];
        __half2 b0 = gl[(size_t)rb.x * 32];
        __half2 b1 = gl[(size_t)rb.y * 32];
        __half2 b2 = gl[(size_t)rb.z * 32];
        __half2 b3 = gl[(size_t)rb.w * 32];
        __half2 pa0 = __hadd2(a0, a1);
        __half2 pa1 = __hadd2(a2, a3);
        __half2 pb0 = __hadd2(b0, b1);
        __half2 pb1 = __hadd2(b2, b3);
        float2 fa0 = __half22float2(pa0);
        float2 fa1 = __half22float2(pa1);
        float2 fb0 = __half22float2(pb0);
        float2 fb1 = __half22float2(pb1);
        unsigned long long q0, q1, q2, q3;
        asm("mov.b64 %0, {%1,%2};" : "=l"(q0) : "f"(fa0.x), "f"(fa0.y));
        asm("mov.b64 %0, {%1,%2};" : "=l"(q1) : "f"(fa1.x), "f"(fa1.y));
        asm("mov.b64 %0, {%1,%2};" : "=l"(q2) : "f"(fb0.x), "f"(fb0.y));
        asm("mov.b64 %0, {%1,%2};" : "=l"(q3) : "f"(fb1.x), "f"(fb1.y));
        asm("add.rn.f32x2 %0, %0, %1;" : "+l"(accp) : "l"(q0));
        asm("add.rn.f32x2 %0, %0, %1;" : "+l"(accp) : "l"(q1));
        asm("add.rn.f32x2 %0, %0, %1;" : "+l"(accp) : "l"(q2));
        asm("add.rn.f32x2 %0, %0, %1;" : "+l"(accp) : "l"(q3));
    }
    if (i < e) {                             // one final quad (pdeg%8 == 4)
        int4 ra = *(const int4*)&d_csr[i];
        __half2 a0 = gl[(size_t)ra.x * 32];
        __half2 a1 = gl[(size_t)ra.y * 32];
        __half2 a2 = gl[(size_t)ra.z * 32];
        __half2 a3 = gl[(size_t)ra.w * 32];
        __half2 p0 = __hadd2(a0, a1);
        __half2 p1 = __hadd2(a2, a3);
        float2 f0 = __half22float2(p0);
        float2 f1 = __half22float2(p1);
        unsigned long long q0, q1;
        asm("mov.b64 %0, {%1,%2};" : "=l"(q0) : "f"(f0.x), "f"(f0.y));
        asm("mov.b64 %0, {%1,%2};" : "=l"(q1) : "f"(f1.x), "f"(f1.y));
        asm("add.rn.f32x2 %0, %0, %1;" : "+l"(accp) : "l"(q0));
        asm("add.rn.f32x2 %0, %0, %1;" : "+l"(accp) : "l"(q1));
    }

    asm("mov.b64 {%0,%1}, %2;" : "=f"(acc.x), "=f"(acc.y) : "l"(accp));

    float2 bb = ((const float2*)b)[lane];
    float dv = d_dinv[w];
    if (mode == 0) {
        float x0 = acc.x * dv + bb.x;  x0 = (x0 > 0.f) ? x0 : expm1f(x0);
        float y0 = acc.y * dv + bb.y;  y0 = (y0 > 0.f) ? y0 : expm1f(y0);
        ((__half2*)outv)[(size_t)w * 32 + lane] = __floats2half2_rn(x0, y0);
    } else {
        ((float2*)outv)[(size_t)w * 32 + lane] =
            make_float2(acc.x * dv + bb.x, acc.y * dv + bb.y);
    }
}

// ---------------------------------------------------------------------------
extern "C" void kernel_launch(void* const* d_in, const int* in_sizes, int n_in,
                              void* d_out, int out_size)
{
    const float* x  = (const float*)d_in[0];
    const int*   ei = (const int*)  d_in[1];
    const float* W1 = (const float*)d_in[2];
    const float* b1 = (const float*)d_in[3];
    const float* W2 = (const float*)d_in[4];
    const float* b2 = (const float*)d_in[5];
    const float* W3 = (const float*)d_in[6];
    const float* b3 = (const float*)d_in[7];

    int n = in_sizes[0] / HH;   // 100000
    int E = in_sizes[1] / 2;    // 1600000
    const int* row = ei;        // sources
    const int* col = ei + E;    // targets

    void *g_p, *A_p, *B_p;
    cudaGetSymbolAddress(&g_p, d_g);
    cudaGetSymbolAddress(&A_p, d_bufA);
    cudaGetSymbolAddress(&B_p, d_bufB);
    __half2* g = (__half2*)g_p;
    __half2* A = (__half2*)A_p;
    __half2* B = (__half2*)B_p;

    int nbE     = (E + 255) / 256;                      // 6250
    int gblocks = (n + 127) / 128;                      // 782
    int ablocks = (n * 32 + 255) / 256;                 // one warp per node

    // launch 1: histogram + csr dummy prefill
    count_hist_kernel<<<nbE, 256>>>(col, E);
    // launch 2: padded scan -> aligned rowptr/cursor + dinv
    scan_kernel<<<NSCAN_BLOCKS, 256>>>(n);
    // launch 3 (fused): layer-1 GEMM + CSR fill
    gemm1_fill_kernel<<<gblocks + nbE, 256>>>(x, W1, g, n, gblocks, row, col, E);
    // launch 4: agg1  <- ncu capture slot
    agg_kernel<<<ablocks, 256>>>(g, A, n, 0, b1, 0);
    // Layer 2
    gemm_f16_kernel<<<gblocks, 256>>>(A, W2, g, n);
    agg_kernel<<<ablocks, 256>>>(g, B, n, 0, b2, 0);
    // Layer 3
    gemm_f16_kernel<<<gblocks, 256>>>(B, W3, g, n);
    agg_kernel<<<ablocks, 256>>>(g, d_out, n, 1, b3, 1);   // + fused reset
}